// round 9
// baseline (speedup 1.0000x reference)
#include <cuda_runtime.h>
#include <cuda_bf16.h>
#include <cstdint>
#include <math.h>

#define BB   2
#define SS   2048
#define DD   1024
#define HH   8
#define EE   4
#define DHH  128
#define TOK  (BB*SS)
#define SCALE 0.29730177875068026f      /* 128^-0.25 */

/* ------------------------------------------------------------------ */
/* scratch (device globals)                                            */
/* ------------------------------------------------------------------ */
__device__ float g_res[TOK * DD];      /* [t, h*128+dh] */
__device__ float g_gv[TOK * HH * EE];
__device__ float g_go[TOK * HH * EE];

/* pre-split activations: [b,h,s,dh] layout */
__device__ __nv_bfloat16 g_qh[TOK * DD], g_ql[TOK * DD];
__device__ __nv_bfloat16 g_kh[TOK * DD], g_kl[TOK * DD];
__device__ __nv_bfloat16 g_vh[TOK * DD], g_vl[TOK * DD];

/* pre-split weights */
__device__ __nv_bfloat16 g_wqh[DD * DD], g_wql[DD * DD];
__device__ __nv_bfloat16 g_wkh[DD * DD], g_wkl[DD * DD];
__device__ __nv_bfloat16 g_wvh[HH * EE * DD * DHH], g_wvl[HH * EE * DD * DHH];
__device__ __nv_bfloat16 g_woh[HH * EE * DHH * DD], g_wol[HH * EE * DHH * DD];

/* ------------------------------------------------------------------ */
/* helpers                                                             */
/* ------------------------------------------------------------------ */
__device__ __forceinline__ uint32_t smem_u32(const void* p) {
    return (uint32_t)__cvta_generic_to_shared(p);
}
__device__ __forceinline__ void ldsm4(uint32_t* r, uint32_t a) {
    asm volatile("ldmatrix.sync.aligned.m8n8.x4.shared.b16 {%0,%1,%2,%3}, [%4];"
                 : "=r"(r[0]), "=r"(r[1]), "=r"(r[2]), "=r"(r[3]) : "r"(a));
}
__device__ __forceinline__ void ldsm4t(uint32_t* r, uint32_t a) {
    asm volatile("ldmatrix.sync.aligned.m8n8.x4.trans.shared.b16 {%0,%1,%2,%3}, [%4];"
                 : "=r"(r[0]), "=r"(r[1]), "=r"(r[2]), "=r"(r[3]) : "r"(a));
}
__device__ __forceinline__ void mma16816(float* d, const uint32_t* a, const uint32_t* b) {
    asm volatile(
        "mma.sync.aligned.m16n8k16.row.col.f32.bf16.bf16.f32 "
        "{%0,%1,%2,%3}, {%4,%5,%6,%7}, {%8,%9}, {%0,%1,%2,%3};"
        : "+f"(d[0]), "+f"(d[1]), "+f"(d[2]), "+f"(d[3])
        : "r"(a[0]), "r"(a[1]), "r"(a[2]), "r"(a[3]), "r"(b[0]), "r"(b[1]));
}
__device__ __forceinline__ uint32_t packbf(float x, float y) {
    __nv_bfloat162 t = __floats2bfloat162_rn(x, y);
    return *reinterpret_cast<uint32_t*>(&t);
}
__device__ __forceinline__ void split_pair(float x, float y, uint32_t& h, uint32_t& l) {
    float hx = __bfloat162float(__float2bfloat16(x));
    float hy = __bfloat162float(__float2bfloat16(y));
    h = packbf(hx, hy);
    l = packbf(x - hx, y - hy);
}
__device__ __forceinline__ void cpa16(uint32_t dst, const void* src) {
    asm volatile("cp.async.cg.shared.global [%0], [%1], 16;" :: "r"(dst), "l"(src));
}
#define CP_COMMIT() asm volatile("cp.async.commit_group;" ::: "memory")
#define CP_WAIT0()  asm volatile("cp.async.wait_group 0;" ::: "memory")

/* ------------------------------------------------------------------ */
/* Weight pre-split: fp32 -> bf16 hi/lo                                */
/* ------------------------------------------------------------------ */
template <int W>
__global__ void wsplit(const float4* __restrict__ src, int n4) {
    int i = blockIdx.x * 256 + threadIdx.x;
    if (i >= n4) return;
    float4 x = src[i];
    uint32_t h0, l0, h1, l1;
    split_pair(x.x, x.y, h0, l0);
    split_pair(x.z, x.w, h1, l1);
    uint2* dh; uint2* dl;
    if (W == 0)      { dh = (uint2*)g_wqh; dl = (uint2*)g_wql; }
    else if (W == 1) { dh = (uint2*)g_wkh; dl = (uint2*)g_wkl; }
    else if (W == 2) { dh = (uint2*)g_wvh; dl = (uint2*)g_wvl; }
    else             { dh = (uint2*)g_woh; dl = (uint2*)g_wol; }
    dh[i] = make_uint2(h0, h1);
    dl[i] = make_uint2(l0, l1);
}

/* ------------------------------------------------------------------ */
/* Gates                                                               */
/* ------------------------------------------------------------------ */
__global__ void gates_kernel(const float* __restrict__ k_src,
                             const float* __restrict__ sel_v,
                             const float* __restrict__ q_src,
                             const float* __restrict__ sel_o) {
    int w = threadIdx.x >> 5;
    int lane = threadIdx.x & 31;
    int t = blockIdx.x * 8 + w;

    const float* x; const float* sel; float* out;
    if (blockIdx.y == 0) { x = k_src; sel = sel_v; out = g_gv; }
    else                 { x = q_src; sel = sel_o; out = g_go; }

    const float4* xr = (const float4*)(x + (size_t)t * DD);
    const float4* sr = (const float4*)(sel + (size_t)lane * DD);
    float acc = 0.f;
#pragma unroll 8
    for (int i = 0; i < DD / 4; i++) {
        float4 a = xr[i], b = sr[i];
        acc += a.x * b.x + a.y * b.y + a.z * b.z + a.w * b.w;
    }
    float g = 1.f / (1.f + __expf(-acc));

    __shared__ float sh[8][32];
    sh[w][lane] = g;
    __syncwarp();

    if (lane < HH) {
        float vv[4];
#pragma unroll
        for (int e = 0; e < 4; e++) vv[e] = sh[w][lane * 4 + e];
        int i1 = 0; float m1 = vv[0];
#pragma unroll
        for (int e = 1; e < 4; e++) if (vv[e] > m1) { m1 = vv[e]; i1 = e; }
        int i2 = -1; float m2 = -1e30f;
#pragma unroll
        for (int e = 0; e < 4; e++) if (e != i1 && vv[e] > m2) { m2 = vv[e]; i2 = e; }
#pragma unroll
        for (int e = 0; e < 4; e++)
            out[(size_t)t * 32 + lane * 4 + e] = (e == i1 || e == i2) ? vv[e] : 0.f;
    }
}

/* ------------------------------------------------------------------ */
/* Tensor-core GEMM (mma.sync), block 128x128, Kc=32, split bf16.      */
/* ------------------------------------------------------------------ */
#define ASTR 40
#define BSTR 136

template <int MODE>
__global__ void __launch_bounds__(256)
tc_gemm(const float* __restrict__ A,
        float* __restrict__ C) {
    constexpr int KT = (MODE <= 1) ? 1024 : 4096;

    __shared__ __nv_bfloat16 Ah[128 * ASTR];
    __shared__ __nv_bfloat16 Al[128 * ASTR];
    __shared__ __nv_bfloat16 Bh[128 * ASTR];
    __shared__ __nv_bfloat16 Bl[128 * ASTR];

    int tid = threadIdx.x;
    int warp = tid >> 5, lane = tid & 31;
    int wm = warp & 3, wn = warp >> 2;
    int row0 = blockIdx.y * 128;
    int col0 = blockIdx.x * 128;
    int hz = blockIdx.z;

    const float* gates = (MODE == 2) ? g_gv : g_go;
    const __nv_bfloat16 *Bph, *Bpl;
    if (MODE == 0)      { Bph = g_wqh; Bpl = g_wql; }
    else if (MODE == 1) { Bph = g_wkh; Bpl = g_wkl; }
    else if (MODE == 2) { Bph = g_wvh + (size_t)hz * (EE * DD * DHH);
                          Bpl = g_wvl + (size_t)hz * (EE * DD * DHH); }
    else                { Bph = g_woh; Bpl = g_wol; }

    float d[2][8][4];
#pragma unroll
    for (int i = 0; i < 2; i++)
#pragma unroll
        for (int j = 0; j < 8; j++)
#pragma unroll
            for (int c = 0; c < 4; c++) d[i][j][c] = 0.f;

    for (int k0 = 0; k0 < KT; k0 += 32) {
#pragma unroll
        for (int it = 0; it < 4; it++) {
            int idx = it * 256 + tid;
            int r = idx >> 3, c4 = (idx & 7) * 4;
            int kg = k0 + c4;
            int rt = row0 + r;
            const float* src;
            float gm = 1.f;
            if (MODE <= 1) {
                src = A + (size_t)rt * 1024 + kg;
            } else if (MODE == 2) {
                src = A + (size_t)rt * 1024 + (kg & 1023);
                gm = gates[(size_t)rt * 32 + hz * 4 + (kg >> 10)];
            } else {
                int hh = kg >> 9, e = (kg >> 7) & 3, dh = kg & 127;
                src = g_res + (size_t)rt * 1024 + hh * 128 + dh;
                gm = gates[(size_t)rt * 32 + hh * 4 + e];
            }
            float4 x = *(const float4*)src;
            x.x *= gm; x.y *= gm; x.z *= gm; x.w *= gm;
            uint32_t h0, l0, h1, l1;
            split_pair(x.x, x.y, h0, l0);
            split_pair(x.z, x.w, h1, l1);
            *(uint32_t*)&Ah[r * ASTR + c4] = h0;
            *(uint32_t*)&Ah[r * ASTR + c4 + 2] = h1;
            *(uint32_t*)&Al[r * ASTR + c4] = l0;
            *(uint32_t*)&Al[r * ASTR + c4 + 2] = l1;
        }
        if (MODE <= 1) {
#pragma unroll
            for (int it = 0; it < 2; it++) {
                int idx = it * 256 + tid;
                int r = idx >> 2, c8 = (idx & 3) * 8;
                size_t so = (size_t)(col0 + r) * 1024 + k0 + c8;
                *(uint4*)&Bh[r * ASTR + c8] = *(const uint4*)(Bph + so);
                *(uint4*)&Bl[r * ASTR + c8] = *(const uint4*)(Bpl + so);
            }
        } else {
            constexpr int NLD = (MODE == 2) ? 128 : 1024;
#pragma unroll
            for (int it = 0; it < 2; it++) {
                int idx = it * 256 + tid;
                int kr = idx >> 4, c8 = (idx & 15) * 8;
                size_t so = (size_t)(k0 + kr) * NLD + col0 + c8;
                *(uint4*)&Bh[kr * BSTR + c8] = *(const uint4*)(Bph + so);
                *(uint4*)&Bl[kr * BSTR + c8] = *(const uint4*)(Bpl + so);
            }
        }
        __syncthreads();

#pragma unroll
        for (int ks = 0; ks < 2; ks++) {
            uint32_t ah[2][4], al[2][4];
#pragma unroll
            for (int mf = 0; mf < 2; mf++) {
                int off = (wm * 32 + mf * 16 + (lane & 15)) * ASTR + ks * 16 + (lane >> 4) * 8;
                ldsm4(ah[mf], smem_u32(&Ah[off]));
                ldsm4(al[mf], smem_u32(&Al[off]));
            }
            uint32_t bfh[16], bfl[16];
            if (MODE <= 1) {
#pragma unroll
                for (int nf2 = 0; nf2 < 4; nf2++) {
                    int off = (wn * 64 + nf2 * 16 + (lane & 15)) * ASTR + ks * 16 + (lane >> 4) * 8;
                    uint32_t r[4];
                    ldsm4(r, smem_u32(&Bh[off]));
                    bfh[nf2 * 4 + 0] = r[0]; bfh[nf2 * 4 + 1] = r[2];
                    bfh[nf2 * 4 + 2] = r[1]; bfh[nf2 * 4 + 3] = r[3];
                    ldsm4(r, smem_u32(&Bl[off]));
                    bfl[nf2 * 4 + 0] = r[0]; bfl[nf2 * 4 + 1] = r[2];
                    bfl[nf2 * 4 + 2] = r[1]; bfl[nf2 * 4 + 3] = r[3];
                }
            } else {
#pragma unroll
                for (int nf2 = 0; nf2 < 4; nf2++) {
                    int off = (ks * 16 + (lane & 15)) * BSTR + wn * 64 + nf2 * 16 + (lane >> 4) * 8;
                    uint32_t r[4];
                    ldsm4t(r, smem_u32(&Bh[off]));
                    bfh[nf2 * 4 + 0] = r[0]; bfh[nf2 * 4 + 1] = r[1];
                    bfh[nf2 * 4 + 2] = r[2]; bfh[nf2 * 4 + 3] = r[3];
                    ldsm4t(r, smem_u32(&Bl[off]));
                    bfl[nf2 * 4 + 0] = r[0]; bfl[nf2 * 4 + 1] = r[1];
                    bfl[nf2 * 4 + 2] = r[2]; bfl[nf2 * 4 + 3] = r[3];
                }
            }
#pragma unroll
            for (int mf = 0; mf < 2; mf++)
#pragma unroll
                for (int nf = 0; nf < 8; nf++) {
                    mma16816(d[mf][nf], ah[mf], &bfh[nf * 2]);
                    mma16816(d[mf][nf], ah[mf], &bfl[nf * 2]);
                    mma16816(d[mf][nf], al[mf], &bfh[nf * 2]);
                }
        }
        __syncthreads();
    }

    int ri = lane >> 2, c2 = (lane & 3) * 2;
#pragma unroll
    for (int mf = 0; mf < 2; mf++) {
#pragma unroll
        for (int nf = 0; nf < 8; nf++) {
            int col = col0 + wn * 64 + nf * 8 + c2;
#pragma unroll
            for (int hv = 0; hv < 2; hv++) {
                int row = row0 + wm * 32 + mf * 16 + ri + hv * 8;
                float v0 = d[mf][nf][hv * 2];
                float v1 = d[mf][nf][hv * 2 + 1];
                int bidx = row >> 11, sidx = row & 2047;
                if (MODE <= 1) {
                    v0 *= SCALE; v1 *= SCALE;
                    int hh = col >> 7, dh = col & 127;
                    size_t base = (((size_t)bidx * HH + hh) * SS + sidx) * DHH + dh;
                    uint32_t h, l;
                    split_pair(v0, v1, h, l);
                    __nv_bfloat16* dsth = (MODE == 0) ? g_qh : g_kh;
                    __nv_bfloat16* dstl = (MODE == 0) ? g_ql : g_kl;
                    *(uint32_t*)&dsth[base] = h;
                    *(uint32_t*)&dstl[base] = l;
                } else if (MODE == 2) {
                    size_t base = (((size_t)bidx * HH + hz) * SS + sidx) * DHH + col;
                    uint32_t h, l;
                    split_pair(v0, v1, h, l);
                    *(uint32_t*)&g_vh[base] = h;
                    *(uint32_t*)&g_vl[base] = l;
                } else {
                    float2 o = make_float2(v0, v1);
                    *(float2*)&C[(size_t)row * 1024 + col] = o;
                }
            }
        }
    }
}

/* ------------------------------------------------------------------ */
/* FA2 attention: BQ=256, BKV=64, 16 warps (512 thr), Q in smem,       */
/* split K/V single-buffer pipeline, register softmax.                 */
/* smem layout (bf16 elems):                                           */
/*   Qh[256*136], Ql[256*136], Kh[64*136], Kl, Vh, Vl                  */
/* ------------------------------------------------------------------ */
#define QSE   136
#define O_QH  0
#define O_QL  (O_QH + 256 * QSE)
#define O_KH  (O_QL + 256 * QSE)
#define O_KL  (O_KH + 64 * QSE)
#define O_VH  (O_KL + 64 * QSE)
#define O_VL  (O_VH + 64 * QSE)
#define A_ELEMS (O_VL + 64 * QSE)
#define ATTN_BYTES (A_ELEMS * 2)   /* 208896 */

__device__ __forceinline__ void stage64(uint32_t smaddr, int baseElem, int kv0, int tid,
                                        const __nv_bfloat16* sh, const __nv_bfloat16* sl) {
    /* 64 rows x 128 cols, hi+lo: 2048 cpa16 over 512 threads */
#pragma unroll
    for (int it = 0; it < 4; it++) {
        int idx = it * 512 + tid;
        int aid = idx >> 10;
        int rem = idx & 1023;
        int r = rem >> 4, c8 = (rem & 15) * 8;
        const __nv_bfloat16* s = aid ? sl : sh;
        cpa16(smaddr + (uint32_t)(baseElem + aid * (64 * QSE) + r * QSE + c8) * 2,
              s + (size_t)(kv0 + r) * DHH + c8);
    }
}

__global__ void __launch_bounds__(512, 1) attn_fa() {
    extern __shared__ __nv_bfloat16 sm[];
    uint32_t smaddr = smem_u32(sm);

    int tid = threadIdx.x;
    int warp = tid >> 5, lane = tid & 31;
    int bh = blockIdx.y;
    int q0 = blockIdx.x * 256;

    const __nv_bfloat16* qh = g_qh + (size_t)bh * SS * DHH;
    const __nv_bfloat16* ql = g_ql + (size_t)bh * SS * DHH;
    const __nv_bfloat16* kh = g_kh + (size_t)bh * SS * DHH;
    const __nv_bfloat16* kl = g_kl + (size_t)bh * SS * DHH;
    const __nv_bfloat16* vh = g_vh + (size_t)bh * SS * DHH;
    const __nv_bfloat16* vl = g_vl + (size_t)bh * SS * DHH;

    /* ---- stage Q (256 x 128 hi/lo): 8192 cpa16 ---- */
#pragma unroll
    for (int it = 0; it < 16; it++) {
        int idx = it * 512 + tid;
        int aid = idx >> 12;
        int rem = idx & 4095;
        int r = rem >> 4, c8 = (rem & 15) * 8;
        const __nv_bfloat16* s = aid ? ql : qh;
        cpa16(smaddr + (uint32_t)(aid * (256 * QSE) + r * QSE + c8) * 2,
              s + (size_t)(q0 + r) * DHH + c8);
    }
    CP_COMMIT();

    float oacc[16][4];
#pragma unroll
    for (int j = 0; j < 16; j++)
#pragma unroll
        for (int c = 0; c < 4; c++) oacc[j][c] = 0.f;
    float mold[2] = { -1e30f, -1e30f };
    float lsum[2] = { 0.f, 0.f };

    CP_WAIT0();
    __syncthreads();

    /* prologue: K tile 0 */
    stage64(smaddr, O_KH, 0, tid, kh, kl);
    CP_COMMIT();

    for (int kvi = 0; kvi < SS / 64; kvi++) {
        int kv0 = kvi * 64;
        CP_WAIT0();            /* K(i) ready */
        __syncthreads();       /* also: all warps done PV(i-1) -> V buf free */

        /* issue V(i) load; overlaps QK compute */
        stage64(smaddr, O_VH, kv0, tid, vh, vl);
        CP_COMMIT();

        /* S = Q K^T : warp tile 16 x 64, K=128 */
        float sacc[8][4];
#pragma unroll
        for (int j = 0; j < 8; j++)
#pragma unroll
            for (int c = 0; c < 4; c++) sacc[j][c] = 0.f;

#pragma unroll
        for (int ks = 0; ks < 8; ks++) {
            uint32_t qfh[4], qfl[4];
            {
                int off = (warp * 16 + (lane & 15)) * QSE + ks * 16 + (lane >> 4) * 8;
                ldsm4(qfh, smaddr + (uint32_t)(O_QH + off) * 2);
                ldsm4(qfl, smaddr + (uint32_t)(O_QL + off) * 2);
            }
#pragma unroll
            for (int ng = 0; ng < 4; ng++) {
                int off = (ng * 16 + (lane & 15)) * QSE + ks * 16 + (lane >> 4) * 8;
                uint32_t rh[4], rl[4];
                ldsm4(rh, smaddr + (uint32_t)(O_KH + off) * 2);
                ldsm4(rl, smaddr + (uint32_t)(O_KL + off) * 2);
                uint32_t b0h[2] = { rh[0], rh[2] }, b1h[2] = { rh[1], rh[3] };
                uint32_t b0l[2] = { rl[0], rl[2] }, b1l[2] = { rl[1], rl[3] };
                mma16816(sacc[ng * 2], qfh, b0h);
                mma16816(sacc[ng * 2], qfh, b0l);
                mma16816(sacc[ng * 2], qfl, b0h);
                mma16816(sacc[ng * 2 + 1], qfh, b1h);
                mma16816(sacc[ng * 2 + 1], qfh, b1l);
                mma16816(sacc[ng * 2 + 1], qfl, b1h);
            }
        }

        /* register softmax */
        float corr[2];
#pragma unroll
        for (int hf = 0; hf < 2; hf++) {
            float mx = -1e30f;
#pragma unroll
            for (int nf = 0; nf < 8; nf++) {
                mx = fmaxf(mx, sacc[nf][hf * 2]);
                mx = fmaxf(mx, sacc[nf][hf * 2 + 1]);
            }
            mx = fmaxf(mx, __shfl_xor_sync(0xffffffffu, mx, 1));
            mx = fmaxf(mx, __shfl_xor_sync(0xffffffffu, mx, 2));
            float mnew = fmaxf(mold[hf], mx);
            corr[hf] = __expf(mold[hf] - mnew);
            mold[hf] = mnew;
            float ls = 0.f;
#pragma unroll
            for (int nf = 0; nf < 8; nf++) {
                float p0 = __expf(sacc[nf][hf * 2] - mnew);
                float p1 = __expf(sacc[nf][hf * 2 + 1] - mnew);
                sacc[nf][hf * 2] = p0;
                sacc[nf][hf * 2 + 1] = p1;
                ls += p0 + p1;
            }
            ls += __shfl_xor_sync(0xffffffffu, ls, 1);
            ls += __shfl_xor_sync(0xffffffffu, ls, 2);
            lsum[hf] = lsum[hf] * corr[hf] + ls;
        }
#pragma unroll
        for (int nf = 0; nf < 16; nf++) {
            oacc[nf][0] *= corr[0]; oacc[nf][1] *= corr[0];
            oacc[nf][2] *= corr[1]; oacc[nf][3] *= corr[1];
        }

        CP_WAIT0();            /* V(i) ready */
        __syncthreads();       /* also: all warps done QK -> K buf free */

        /* issue K(i+1) load; overlaps PV compute */
        if (kvi + 1 < SS / 64) {
            stage64(smaddr, O_KH, kv0 + 64, tid, kh, kl);
            CP_COMMIT();
        }

        /* O += P V */
#pragma unroll
        for (int kk = 0; kk < 4; kk++) {
            uint32_t ph[4], pl[4];
            split_pair(sacc[kk * 2][0],     sacc[kk * 2][1],     ph[0], pl[0]);
            split_pair(sacc[kk * 2][2],     sacc[kk * 2][3],     ph[1], pl[1]);
            split_pair(sacc[kk * 2 + 1][0], sacc[kk * 2 + 1][1], ph[2], pl[2]);
            split_pair(sacc[kk * 2 + 1][2], sacc[kk * 2 + 1][3], ph[3], pl[3]);
#pragma unroll
            for (int ng = 0; ng < 8; ng++) {
                int off = (kk * 16 + (lane & 15)) * QSE + ng * 16 + (lane >> 4) * 8;
                uint32_t rh[4], rl[4];
                ldsm4t(rh, smaddr + (uint32_t)(O_VH + off) * 2);
                ldsm4t(rl, smaddr + (uint32_t)(O_VL + off) * 2);
                uint32_t b0h[2] = { rh[0], rh[1] }, b1h[2] = { rh[2], rh[3] };
                uint32_t b0l[2] = { rl[0], rl[1] }, b1l[2] = { rl[2], rl[3] };
                mma16816(oacc[ng * 2], ph, b0h);
                mma16816(oacc[ng * 2], ph, b0l);
                mma16816(oacc[ng * 2], pl, b0h);
                mma16816(oacc[ng * 2 + 1], ph, b1h);
                mma16816(oacc[ng * 2 + 1], ph, b1l);
                mma16816(oacc[ng * 2 + 1], pl, b1h);
            }
        }
    }

    /* epilogue: normalize, store g_res[t, h*128+dh] */
    {
        int b = bh >> 3;
        int h2 = bh & 7;
        int ri = lane >> 2;
        int cc = (lane & 3) * 2;
        float li0 = 1.f / lsum[0];
        float li1 = 1.f / lsum[1];
        size_t t0 = (size_t)b * SS + q0 + warp * 16 + ri;
#pragma unroll
        for (int nf = 0; nf < 16; nf++) {
            int col = nf * 8 + cc;
            float2 o0 = make_float2(oacc[nf][0] * li0, oacc[nf][1] * li0);
            float2 o1 = make_float2(oacc[nf][2] * li1, oacc[nf][3] * li1);
            *(float2*)&g_res[t0 * 1024 + h2 * 128 + col] = o0;
            *(float2*)&g_res[(t0 + 8) * 1024 + h2 * 128 + col] = o1;
        }
    }
}

/* ------------------------------------------------------------------ */
extern "C" void kernel_launch(void* const* d_in, const int* in_sizes, int n_in,
                              void* d_out, int out_size) {
    (void)in_sizes; (void)n_in; (void)out_size;
    const float* q_src = (const float*)d_in[0];
    const float* k_src = (const float*)d_in[1];
    const float* v_src = (const float*)d_in[2];
    const float* Wq    = (const float*)d_in[3];
    const float* Wk    = (const float*)d_in[4];
    const float* Wv    = (const float*)d_in[5];
    const float* Wo    = (const float*)d_in[6];
    const float* sel_v = (const float*)d_in[7];
    const float* sel_o = (const float*)d_in[8];
    float* out = (float*)d_out;

    cudaFuncSetAttribute(attn_fa, cudaFuncAttributeMaxDynamicSharedMemorySize, ATTN_BYTES);

    wsplit<0><<<(DD * DD / 4 + 255) / 256, 256>>>((const float4*)Wq, DD * DD / 4);
    wsplit<1><<<(DD * DD / 4 + 255) / 256, 256>>>((const float4*)Wk, DD * DD / 4);
    wsplit<2><<<(HH * EE * DD * DHH / 4 + 255) / 256, 256>>>((const float4*)Wv, HH * EE * DD * DHH / 4);
    wsplit<3><<<(HH * EE * DHH * DD / 4 + 255) / 256, 256>>>((const float4*)Wo, HH * EE * DHH * DD / 4);
    gates_kernel<<<dim3(TOK / 8, 2), 256>>>(k_src, sel_v, q_src, sel_o);

    tc_gemm<0><<<dim3(8, 32), 256>>>(q_src, nullptr);
    tc_gemm<1><<<dim3(8, 32), 256>>>(k_src, nullptr);
    tc_gemm<2><<<dim3(1, 32, 8), 256>>>(v_src, nullptr);
    attn_fa<<<dim3(SS / 256, BB * HH), 512, ATTN_BYTES>>>();
    tc_gemm<3><<<dim3(8, 32), 256>>>(nullptr, out);
}